// round 5
// baseline (speedup 1.0000x reference)
#include <cuda_runtime.h>

// 5x5 masked median filter, 3x1024x1024 fp32.
// Reference semantics: tap (y+dy, x+dx) valid iff 0<=y+dy<=H-2 && 0<=x+dx<=W-2
// (row/col H-1 / W-1 are never valid). Output = mean of the two middle order
// statistics of the valid taps (equals the median element when n is odd).

#define MN fminf
#define MX fmaxf
#define CE(a,b) { float _t = MN(a,b); (b) = MX(a,b); (a) = _t; }

constexpr int H  = 1024;
constexpr int W  = 1024;
constexpr int C  = 3;
constexpr int TX = 32;
constexpr int TY = 8;

__global__ __launch_bounds__(256) void median5_kernel(const float* __restrict__ img,
                                                      float* __restrict__ out)
{
    __shared__ float raw [TY + 4][TX + 4];     // raw tile with +-2 halo (clamped loads)
    __shared__ float scol[TY][TX + 4][5];      // sorted 5-columns per output row

    const int tid = threadIdx.x;               // 0..255
    const int x0  = blockIdx.x * TX;
    const int y0  = blockIdx.y * TY;
    const int ch  = blockIdx.z;
    const float* src = img + (size_t)ch * H * W;

    // ---- Phase 0: load raw tile (clamped coords; masking happens later) ----
    for (int i = tid; i < (TY + 4) * (TX + 4); i += 256) {
        int r = i / (TX + 4), c = i % (TX + 4);
        int gy = y0 - 2 + r; gy = gy < 0 ? 0 : (gy > H - 1 ? H - 1 : gy);
        int gx = x0 - 2 + c; gx = gx < 0 ? 0 : (gx > W - 1 ? W - 1 : gx);
        raw[r][c] = src[gy * W + gx];
    }
    __syncthreads();

    // ---- Phase A: sorted vertical 5-columns (shared by 5 pixels each) ----
    for (int i = tid; i < TY * (TX + 4); i += 256) {
        int yr = i / (TX + 4), xc = i % (TX + 4);
        float v0 = raw[yr + 0][xc];
        float v1 = raw[yr + 1][xc];
        float v2 = raw[yr + 2][xc];
        float v3 = raw[yr + 3][xc];
        float v4 = raw[yr + 4][xc];
        // optimal 9-CE sort5
        CE(v0,v1); CE(v3,v4); CE(v2,v4); CE(v2,v3); CE(v1,v4);
        CE(v0,v3); CE(v0,v2); CE(v1,v3); CE(v1,v2);
        scol[yr][xc][0] = v0; scol[yr][xc][1] = v1; scol[yr][xc][2] = v2;
        scol[yr][xc][3] = v3; scol[yr][xc][4] = v4;
    }
    __syncthreads();

    const int tx = tid & 31, ty = tid >> 5;
    const int x = x0 + tx, y = y0 + ty;

    float med;
    const bool interior = ((unsigned)(y - 2) <= (unsigned)(H - 6)) &&
                          ((unsigned)(x - 2) <= (unsigned)(W - 6));

    if (interior) {
        // Doubly-sorted-matrix median selection.
        // Row-wise rank selection over the 5 sorted columns; median of the 13
        // feasible positions equals the median of all 25 (counting argument).
        float a03, a04, a12, a13, a14, a21, a22, a23, a30, a31, a32, a40, a41;
        {   // row 0: ranks {3,4}
            float q0 = scol[ty][tx+0][0], q1 = scol[ty][tx+1][0], q2 = scol[ty][tx+2][0],
                  q3 = scol[ty][tx+3][0], q4 = scol[ty][tx+4][0];
            CE(q0,q1); CE(q2,q3);
            float mx4 = MX(q1,q3);
            float sec = MX(MN(q1,q3), MX(q0,q2));
            a04 = MX(mx4, q4);
            a03 = MX(sec, MN(mx4, q4));
        }
        {   // row 1: ranks {2,3,4}
            float q0 = scol[ty][tx+0][1], q1 = scol[ty][tx+1][1], q2 = scol[ty][tx+2][1],
                  q3 = scol[ty][tx+3][1], q4 = scol[ty][tx+4][1];
            CE(q0,q1); CE(q2,q3);
            float x2p = MX(q0,q2);
            float x1p = MN(q1,q3), x3p = MX(q1,q3);
            float s1 = MN(x1p,x2p), s2 = MX(x1p,x2p), s3 = x3p;
            a14 = MX(s3, q4);
            a13 = MX(s2, MN(s3, q4));
            a12 = MN(MX(q4, s1), s2);
        }
        {   // row 2: ranks {1,2,3}
            float q0 = scol[ty][tx+0][2], q1 = scol[ty][tx+1][2], q2 = scol[ty][tx+2][2],
                  q3 = scol[ty][tx+3][2], q4 = scol[ty][tx+4][2];
            CE(q0,q1); CE(q2,q3); CE(q0,q2); CE(q1,q3); CE(q1,q2);  // full sort4
            a21 = MN(q1, MX(q0, q4));
            a22 = MN(MX(q4, q1), q2);
            a23 = MX(q2, MN(q3, q4));
        }
        {   // row 3: ranks {0,1,2}
            float q0 = scol[ty][tx+0][3], q1 = scol[ty][tx+1][3], q2 = scol[ty][tx+2][3],
                  q3 = scol[ty][tx+3][3], q4 = scol[ty][tx+4][3];
            CE(q0,q1); CE(q2,q3);
            float y1p = MN(q1,q3);
            float s0 = MN(q0,q2), y2p = MX(q0,q2);
            float t1 = MN(y2p,y1p), t2 = MX(y2p,y1p);
            a30 = MN(s0, q4);
            a31 = MN(t1, MX(s0, q4));
            a32 = MX(MN(q4, t2), t1);
        }
        {   // row 4: ranks {0,1}
            float q0 = scol[ty][tx+0][4], q1 = scol[ty][tx+1][4], q2 = scol[ty][tx+2][4],
                  q3 = scol[ty][tx+3][4], q4 = scol[ty][tx+4][4];
            CE(q0,q1); CE(q2,q3);
            float mn4 = MN(q0,q2);
            float sec = MN(MX(q0,q2), MN(q1,q3));
            a40 = MN(mn4, q4);
            a41 = MN(sec, MX(mn4, q4));
        }
        // Level 2: median of the 13 candidates (5 chains 2/3/3/3/2, +-inf padded
        // to a col-sorted 3x5) -> median of 7 candidates.
        // L0 = [-inf, a21, a12, a03, a04] -> ranks {3,4} == top-2 of 4 reals
        float u  = MN(a21, a12), U  = MX(a21, a12);
        float b04 = MX(U, a04);
        float b03 = MX(MN(U, a04), MX(u, a03));
        // L2 = [a40, a41, a32, a23, +inf] -> ranks {0,1} == bottom-2 of 4 reals
        float w  = MN(a32, a23), Wv = MX(a32, a23);
        float b20 = MN(a40, w);
        float b21 = MN(MX(a40, w), MN(a41, Wv));
        // L1 = [a30, a31, a22, a13, a14] -> middle-3 sorted
        float m0 = MN(a30, a13), m3 = MX(a31, a14);
        float tA = MX(a30, a13), tB = MN(a31, a14);
        float m1 = MN(tA, tB), m2 = MX(tA, tB);
        float b11 = MN(m1, MX(m0, a22));
        float b12 = MN(MX(a22, m1), m2);
        float b13 = MX(m2, MN(m3, a22));
        // Level 3: median of 7 = chains (b20<=b21),(b11<=b12<=b13),(b03<=b04)
        // padded to 3x3 -> med3 of antidiagonal.
        float e0 = MX(b11, b03);
        float e2 = MN(b21, b13);
        float mnp = MN(b20, b12);
        float e1 = MX(mnp, MN(MX(b20, b12), b04));     // med3(b20,b12,b04)
        float mne = MN(e0, e1);
        med = MX(mne, MN(MX(e0, e1), e2));             // med3(e0,e1,e2)
    } else {
        // ---- Boundary path (~1% of pixels): inf-masked partial selection sort ----
        const float FINF = __int_as_float(0x7f800000);
        float v[25];
        #pragma unroll
        for (int dy = -2; dy <= 2; dy++) {
            #pragma unroll
            for (int dx = -2; dx <= 2; dx++) {
                int yy = y + dy, xx = x + dx;
                bool ok = (yy >= 0) && (yy <= H - 2) && (xx >= 0) && (xx <= W - 2);
                float val = raw[ty + 2 + dy][tx + 2 + dx];
                v[(dy + 2) * 5 + (dx + 2)] = ok ? val : FINF;
            }
        }
        // place ranks 0..12 (max needed rank is 12 since n <= 25)
        #pragma unroll
        for (int i = 0; i < 13; i++) {
            #pragma unroll
            for (int j = i + 1; j < 25; j++) {
                CE(v[i], v[j]);
            }
        }
        int ylo = y - 2 < 0 ? 0 : y - 2;
        int yhi = y + 2 > H - 2 ? H - 2 : y + 2;
        int xlo = x - 2 < 0 ? 0 : x - 2;
        int xhi = x + 2 > W - 2 ? W - 2 : x + 2;
        int n  = (yhi - ylo + 1) * (xhi - xlo + 1);
        int li = (n - 1) >> 1, hi = n >> 1;
        float lo = v[0], hh = v[0];
        #pragma unroll
        for (int k = 0; k < 13; k++) {
            if (k == li) lo = v[k];
            if (k == hi) hh = v[k];
        }
        med = 0.5f * (lo + hh);
    }

    out[(size_t)ch * H * W + (size_t)y * W + x] = med;
}

extern "C" void kernel_launch(void* const* d_in, const int* in_sizes, int n_in,
                              void* d_out, int out_size)
{
    (void)in_sizes; (void)n_in; (void)out_size;
    const float* img = (const float*)d_in[0];
    float* out = (float*)d_out;
    dim3 block(256, 1, 1);
    dim3 grid(W / TX, H / TY, C);
    median5_kernel<<<grid, block>>>(img, out);
}

// round 8
// speedup vs baseline: 1.0965x; 1.0965x over previous
#include <cuda_runtime.h>
#include <cuda_fp16.h>

// 5x5 masked median filter, 3x1024x1024 fp32, f16x2-packed (2 pixels/lane).
// Reference semantics: tap (y+dy, x+dx) valid iff 0<=y+dy<=H-2 && 0<=x+dx<=W-2.
// Output = mean of the two middle order statistics of valid taps.
// Interior (n=25): exact doubly-sorted-matrix selection, computed in half2
// (two pixels packed per register -> HMNMX2 does 2 pixels per instruction).
// Boundary (~1%): exact fp32 inf-masked partial selection sort.

#define MN2 __hmin2
#define MX2 __hmax2
#define CE2(a,b) { half2 _t2 = MN2(a,b); (b) = MX2(a,b); (a) = _t2; }
#define MNf fminf
#define MXf fmaxf
#define CEf(a,b) { float _tf = MNf(a,b); (b) = MXf(a,b); (a) = _tf; }

constexpr int H   = 1024;
constexpr int W   = 1024;
constexpr int C   = 3;
constexpr int TXP = 64;          // output pixels per block in x (32 lanes x 2)
constexpr int TY  = 8;           // output rows per block
constexpr int RCOLS = TXP + 4;   // 68 raw columns (with +-2 halo)
constexpr int PCOLS = 36;        // packed half2 columns: pc -> (col pc, col pc+32)

// exact fp32 boundary path (also correct for interior, just slower)
__device__ __forceinline__ float boundary_median(const float (*raw)[RCOLS],
                                                 int ty, int lc, int x, int y)
{
    const float FINF = __int_as_float(0x7f800000);
    float v[25];
    #pragma unroll
    for (int dy = -2; dy <= 2; dy++) {
        #pragma unroll
        for (int dx = -2; dx <= 2; dx++) {
            int yy = y + dy, xx = x + dx;
            bool ok = (yy >= 0) && (yy <= H - 2) && (xx >= 0) && (xx <= W - 2);
            float val = raw[ty + 2 + dy][lc + dx];
            v[(dy + 2) * 5 + (dx + 2)] = ok ? val : FINF;
        }
    }
    #pragma unroll
    for (int i = 0; i < 13; i++) {
        #pragma unroll
        for (int j = i + 1; j < 25; j++) {
            CEf(v[i], v[j]);
        }
    }
    int ylo = y - 2 < 0 ? 0 : y - 2;
    int yhi = y + 2 > H - 2 ? H - 2 : y + 2;
    int xlo = x - 2 < 0 ? 0 : x - 2;
    int xhi = x + 2 > W - 2 ? W - 2 : x + 2;
    int n  = (yhi - ylo + 1) * (xhi - xlo + 1);
    int li = (n - 1) >> 1, hi = n >> 1;
    float lo = v[0], hh = v[0];
    #pragma unroll
    for (int k = 0; k < 13; k++) {
        if (k == li) lo = v[k];
        if (k == hi) hh = v[k];
    }
    return 0.5f * (lo + hh);
}

__global__ __launch_bounds__(256) void median5_kernel(const float* __restrict__ img,
                                                      float* __restrict__ out)
{
    __shared__ float raw [TY + 4][RCOLS];      // fp32 raw tile with halo (clamped)
    __shared__ half2 scol[TY][PCOLS][5];       // packed sorted 5-columns

    const int tid = threadIdx.x;               // 0..255
    const int x0  = blockIdx.x * TXP;
    const int y0  = blockIdx.y * TY;
    const int ch  = blockIdx.z;
    const float* src = img + (size_t)ch * H * W;

    // ---- Phase 0: load raw tile (clamped coords; masking happens later) ----
    for (int i = tid; i < (TY + 4) * RCOLS; i += 256) {
        int r = i / RCOLS, c = i % RCOLS;
        int gy = y0 - 2 + r; gy = gy < 0 ? 0 : (gy > H - 1 ? H - 1 : gy);
        int gx = x0 - 2 + c; gx = gx < 0 ? 0 : (gx > W - 1 ? W - 1 : gx);
        raw[r][c] = src[gy * W + gx];
    }
    __syncthreads();

    // ---- Phase A: packed sorted vertical 5-columns ----
    // packed column pc holds (global col x0-2+pc) in .lo and (x0+30+pc) in .hi
    for (int i = tid; i < TY * PCOLS; i += 256) {
        int yr = i / PCOLS, pc = i % PCOLS;
        half2 v0 = __floats2half2_rn(raw[yr + 0][pc], raw[yr + 0][pc + 32]);
        half2 v1 = __floats2half2_rn(raw[yr + 1][pc], raw[yr + 1][pc + 32]);
        half2 v2 = __floats2half2_rn(raw[yr + 2][pc], raw[yr + 2][pc + 32]);
        half2 v3 = __floats2half2_rn(raw[yr + 3][pc], raw[yr + 3][pc + 32]);
        half2 v4 = __floats2half2_rn(raw[yr + 4][pc], raw[yr + 4][pc + 32]);
        // optimal 9-CE sort5 (independently per half)
        CE2(v0,v1); CE2(v3,v4); CE2(v2,v4); CE2(v2,v3); CE2(v1,v4);
        CE2(v0,v3); CE2(v0,v2); CE2(v1,v3); CE2(v1,v2);
        scol[yr][pc][0] = v0; scol[yr][pc][1] = v1; scol[yr][pc][2] = v2;
        scol[yr][pc][3] = v3; scol[yr][pc][4] = v4;
    }
    __syncthreads();

    const int tx = tid & 31, ty = tid >> 5;
    const int x  = x0 + tx;          // lo pixel
    const int xh = x + 32;           // hi pixel
    const int y  = y0 + ty;

    const bool yint   = ((unsigned)(y  - 2) <= (unsigned)(H - 6));
    const bool int_lo = yint && ((unsigned)(x  - 2) <= (unsigned)(W - 6));
    const bool int_hi = yint && ((unsigned)(xh - 2) <= (unsigned)(W - 6));

    float* orow = out + (size_t)ch * H * W + (size_t)y * W;

    if (int_lo && int_hi) {
        // ---- Packed doubly-sorted-matrix median selection (both halves) ----
        half2 a03, a04, a12, a13, a14, a21, a22, a23, a30, a31, a32, a40, a41;
        {   // row 0: ranks {3,4}
            half2 q0 = scol[ty][tx+0][0], q1 = scol[ty][tx+1][0], q2 = scol[ty][tx+2][0],
                  q3 = scol[ty][tx+3][0], q4 = scol[ty][tx+4][0];
            CE2(q0,q1); CE2(q2,q3);
            half2 mx4 = MX2(q1,q3);
            half2 sec = MX2(MN2(q1,q3), MX2(q0,q2));
            a04 = MX2(mx4, q4);
            a03 = MX2(sec, MN2(mx4, q4));
        }
        {   // row 1: ranks {2,3,4}
            half2 q0 = scol[ty][tx+0][1], q1 = scol[ty][tx+1][1], q2 = scol[ty][tx+2][1],
                  q3 = scol[ty][tx+3][1], q4 = scol[ty][tx+4][1];
            CE2(q0,q1); CE2(q2,q3);
            half2 x2p = MX2(q0,q2);
            half2 x1p = MN2(q1,q3), x3p = MX2(q1,q3);
            half2 s1 = MN2(x1p,x2p), s2 = MX2(x1p,x2p), s3 = x3p;
            a14 = MX2(s3, q4);
            a13 = MX2(s2, MN2(s3, q4));
            a12 = MN2(MX2(q4, s1), s2);
        }
        {   // row 2: ranks {1,2,3}
            half2 q0 = scol[ty][tx+0][2], q1 = scol[ty][tx+1][2], q2 = scol[ty][tx+2][2],
                  q3 = scol[ty][tx+3][2], q4 = scol[ty][tx+4][2];
            CE2(q0,q1); CE2(q2,q3); CE2(q0,q2); CE2(q1,q3); CE2(q1,q2);  // sort4
            a21 = MN2(q1, MX2(q0, q4));
            a22 = MN2(MX2(q4, q1), q2);
            a23 = MX2(q2, MN2(q3, q4));
        }
        {   // row 3: ranks {0,1,2}
            half2 q0 = scol[ty][tx+0][3], q1 = scol[ty][tx+1][3], q2 = scol[ty][tx+2][3],
                  q3 = scol[ty][tx+3][3], q4 = scol[ty][tx+4][3];
            CE2(q0,q1); CE2(q2,q3);
            half2 y1p = MN2(q1,q3);
            half2 s0 = MN2(q0,q2), y2p = MX2(q0,q2);
            half2 t1 = MN2(y2p,y1p), t2 = MX2(y2p,y1p);
            a30 = MN2(s0, q4);
            a31 = MN2(t1, MX2(s0, q4));
            a32 = MX2(MN2(q4, t2), t1);
        }
        {   // row 4: ranks {0,1}
            half2 q0 = scol[ty][tx+0][4], q1 = scol[ty][tx+1][4], q2 = scol[ty][tx+2][4],
                  q3 = scol[ty][tx+3][4], q4 = scol[ty][tx+4][4];
            CE2(q0,q1); CE2(q2,q3);
            half2 mn4 = MN2(q0,q2);
            half2 sec = MN2(MX2(q0,q2), MN2(q1,q3));
            a40 = MN2(mn4, q4);
            a41 = MN2(sec, MX2(mn4, q4));
        }
        // Level 2: median of 13 candidates -> median of 7
        half2 u  = MN2(a21, a12), U  = MX2(a21, a12);
        half2 b04 = MX2(U, a04);
        half2 b03 = MX2(MN2(U, a04), MX2(u, a03));
        half2 w  = MN2(a32, a23), Wv = MX2(a32, a23);
        half2 b20 = MN2(a40, w);
        half2 b21 = MN2(MX2(a40, w), MN2(a41, Wv));
        half2 m0 = MN2(a30, a13), m3 = MX2(a31, a14);
        half2 tA = MX2(a30, a13), tB = MN2(a31, a14);
        half2 m1 = MN2(tA, tB), m2 = MX2(tA, tB);
        half2 b11 = MN2(m1, MX2(m0, a22));
        half2 b12 = MN2(MX2(a22, m1), m2);
        half2 b13 = MX2(m2, MN2(m3, a22));
        // Level 3: median of 7 via med3 of antidiagonal of padded 3x3
        half2 e0 = MX2(b11, b03);
        half2 e2 = MN2(b21, b13);
        half2 mnp = MN2(b20, b12);
        half2 e1 = MX2(mnp, MN2(MX2(b20, b12), b04));   // med3(b20,b12,b04)
        half2 mne = MN2(e0, e1);
        half2 med = MX2(mne, MN2(MX2(e0, e1), e2));     // med3(e0,e1,e2)

        orow[x]  = __low2float(med);
        orow[xh] = __high2float(med);
    } else {
        // ---- Boundary path: exact fp32 per pixel ----
        orow[x]  = boundary_median(raw, ty, tx + 2,  x,  y);
        orow[xh] = boundary_median(raw, ty, tx + 34, xh, y);
    }
}

extern "C" void kernel_launch(void* const* d_in, const int* in_sizes, int n_in,
                              void* d_out, int out_size)
{
    (void)in_sizes; (void)n_in; (void)out_size;
    const float* img = (const float*)d_in[0];
    float* out = (float*)d_out;
    dim3 block(256, 1, 1);
    dim3 grid(W / TXP, H / TY, C);
    median5_kernel<<<grid, block>>>(img, out);
}